// round 5
// baseline (speedup 1.0000x reference)
#include <cuda_runtime.h>

#define NN 50000
#define NE 800000
#define HD 128

// ---------------- scratch (device globals; no allocation allowed) ----------
__device__ int   g_is64;
__device__ int   g_deg[NN];
__device__ int   g_fill[NN];
__device__ float g_dinv[NN];
__device__ int   g_rowptr[NN + 1];
__device__ int   g_csr_src[NE];
__device__ int   g_csr_dst[NE];
__device__ float g_csr_norm[NE];
__device__ float g_adst[(size_t)NN * HD];   // x @ W1[0:128,:]
__device__ float g_asrc[(size_t)NN * HD];   // x @ W1[128:256,:]
__device__ float g_Y[(size_t)NN * 4 * HD];  // [x | A x | A^2 x | A^3 x], row stride 512
__device__ int   g_bsum[64];

#define SCAN_NB ((NN + 1023) / 1024)
#define YS 512   // row stride of g_Y in floats

// ---------------- edge-index dtype detection -------------------------------
// jnp.int64 under default JAX config materializes as int32. Values < 50000,
// so if the buffer is truly int64(LE), every odd 32-bit word is 0. For int32,
// odd words are uniform random node ids — all-zero is impossible in practice.
__global__ void detect_kernel(const int* __restrict__ w) {
    if (threadIdx.x == 0) {
        int all0 = 1;
        for (int i = 1; i < 256; i += 2)
            if (w[i] != 0) all0 = 0;
        g_is64 = all0;
    }
}

__device__ __forceinline__ int load_idx(const void* ei, long long i, int is64) {
    if (is64) return (int)((const long long*)ei)[i];
    return ((const int*)ei)[i];
}

// ---------------- small prep kernels ---------------------------------------
__global__ void zero_kernel() {
    int i = blockIdx.x * blockDim.x + threadIdx.x;
    if (i < NN) { g_deg[i] = 0; g_fill[i] = 0; }
}

__global__ void deg_kernel(const void* __restrict__ ei) {
    int e = blockIdx.x * blockDim.x + threadIdx.x;
    int is64 = g_is64;
    if (e < NE) {
        int d = load_idx(ei, (long long)NE + e, is64);
        atomicAdd(&g_deg[d], 1);
    }
}

__global__ void dinv_kernel() {
    int n = blockIdx.x * blockDim.x + threadIdx.x;
    if (n < NN) {
        int dg = g_deg[n];
        g_dinv[n] = (dg > 0) ? rsqrtf((float)dg) : 0.0f;
    }
}

__global__ void scan1_kernel() {
    __shared__ int sh[1024];
    int i = blockIdx.x * 1024 + threadIdx.x;
    int v = (i < NN) ? g_deg[i] : 0;
    sh[threadIdx.x] = v;
    __syncthreads();
    for (int off = 1; off < 1024; off <<= 1) {
        int t = (threadIdx.x >= off) ? sh[threadIdx.x - off] : 0;
        __syncthreads();
        sh[threadIdx.x] += t;
        __syncthreads();
    }
    if (i < NN) g_rowptr[i] = sh[threadIdx.x] - v;  // exclusive within block
    if (threadIdx.x == 1023) g_bsum[blockIdx.x] = sh[1023];
}

__global__ void scan2_kernel() {
    if (threadIdx.x == 0) {
        int acc = 0;
        for (int b = 0; b < SCAN_NB; b++) { int t = g_bsum[b]; g_bsum[b] = acc; acc += t; }
    }
}

__global__ void scan3_kernel() {
    int i = blockIdx.x * blockDim.x + threadIdx.x;
    if (i < NN) g_rowptr[i] += g_bsum[i / 1024];
    if (i == 0) g_rowptr[NN] = NE;
}

__global__ void fill_kernel(const void* __restrict__ ei) {
    int e = blockIdx.x * blockDim.x + threadIdx.x;
    int is64 = g_is64;
    if (e < NE) {
        int s = load_idx(ei, e, is64);
        int d = load_idx(ei, (long long)NE + e, is64);
        int pos = g_rowptr[d] + atomicAdd(&g_fill[d], 1);
        g_csr_src[pos]  = s;
        g_csr_dst[pos]  = d;
        g_csr_norm[pos] = g_dinv[s] * g_dinv[d];
    }
}

// init Y[:,0:128] = deg[n] * b2  (per-edge bias b2 summed deg[n] times)
__global__ void init_y0_kernel(const float* __restrict__ b2) {
    int idx = blockIdx.x * blockDim.x + threadIdx.x;  // float4 units, NN*32 total
    if (idx < NN * 32) {
        int n = idx >> 5, c4 = idx & 31;
        float dg = (float)g_deg[n];
        float4 b = *(const float4*)(b2 + c4 * 4);
        float4 o; o.x = dg * b.x; o.y = dg * b.y; o.z = dg * b.z; o.w = dg * b.w;
        *(float4*)(g_Y + (size_t)n * YS + c4 * 4) = o;
    }
}

// ---------------- dense GEMM: C[M,128] = A[M,K] @ B[K,128] (+bias)(+relu) --
// BM=128, BN=128, BK=16, 256 threads, 8x8 per-thread tile.
// A tile stored k-major (transposed) in smem; double-buffered smem tiles ->
// one __syncthreads per K tile, gmem loads overlap FFMA compute.
__global__ void gemm128x128(const float* __restrict__ A, int lda,
                            const float* __restrict__ B,
                            const float* __restrict__ bias,
                            float* __restrict__ C, int ldc,
                            int M, int K, int relu) {
    __shared__ float As[2][16][132];    // [buf][k][m], padded
    __shared__ float Bs[2][16][128];    // [buf][k][n]
    int tid = threadIdx.x;
    int tx = tid & 15, ty = tid >> 4;
    int m0 = ty * 8, n0 = tx * 8;
    int rowBase = blockIdx.x * 128;

    // A-load addressing: thread covers rows rA0/rA1, k-group k4A
    int slotA0 = tid * 2, slotA1 = tid * 2 + 1;
    int rA0 = slotA0 >> 2, k4A0 = slotA0 & 3;
    int rA1 = slotA1 >> 2, k4A1 = slotA1 & 3;
    // B-load addressing
    int kkB0 = tid >> 5,        c4B0 = tid & 31;
    int kkB1 = (tid + 256) >> 5, c4B1 = (tid + 256) & 31;

    float acc[8][8];
#pragma unroll
    for (int i = 0; i < 8; i++)
#pragma unroll
        for (int j = 0; j < 8; j++) acc[i][j] = 0.0f;

    // ---- load tile 0 into buffer 0 ----
    {
        int grow0 = rowBase + rA0, grow1 = rowBase + rA1;
        float4 v0 = make_float4(0.f, 0.f, 0.f, 0.f);
        float4 v1 = make_float4(0.f, 0.f, 0.f, 0.f);
        if (grow0 < M) v0 = *(const float4*)(A + (size_t)grow0 * lda + k4A0 * 4);
        if (grow1 < M) v1 = *(const float4*)(A + (size_t)grow1 * lda + k4A1 * 4);
        As[0][k4A0 * 4 + 0][rA0] = v0.x; As[0][k4A0 * 4 + 1][rA0] = v0.y;
        As[0][k4A0 * 4 + 2][rA0] = v0.z; As[0][k4A0 * 4 + 3][rA0] = v0.w;
        As[0][k4A1 * 4 + 0][rA1] = v1.x; As[0][k4A1 * 4 + 1][rA1] = v1.y;
        As[0][k4A1 * 4 + 2][rA1] = v1.z; As[0][k4A1 * 4 + 3][rA1] = v1.w;
        *(float4*)&Bs[0][kkB0][c4B0 * 4] = *(const float4*)(B + (size_t)kkB0 * 128 + c4B0 * 4);
        *(float4*)&Bs[0][kkB1][c4B1 * 4] = *(const float4*)(B + (size_t)kkB1 * 128 + c4B1 * 4);
    }
    __syncthreads();

    int buf = 0;
    for (int kt = 0; kt < K; kt += 16) {
        // ---- prefetch next tile into buf^1 (overlaps with compute below) ----
        if (kt + 16 < K) {
            int nb = buf ^ 1;
            int grow0 = rowBase + rA0, grow1 = rowBase + rA1;
            float4 v0 = make_float4(0.f, 0.f, 0.f, 0.f);
            float4 v1 = make_float4(0.f, 0.f, 0.f, 0.f);
            if (grow0 < M) v0 = *(const float4*)(A + (size_t)grow0 * lda + kt + 16 + k4A0 * 4);
            if (grow1 < M) v1 = *(const float4*)(A + (size_t)grow1 * lda + kt + 16 + k4A1 * 4);
            As[nb][k4A0 * 4 + 0][rA0] = v0.x; As[nb][k4A0 * 4 + 1][rA0] = v0.y;
            As[nb][k4A0 * 4 + 2][rA0] = v0.z; As[nb][k4A0 * 4 + 3][rA0] = v0.w;
            As[nb][k4A1 * 4 + 0][rA1] = v1.x; As[nb][k4A1 * 4 + 1][rA1] = v1.y;
            As[nb][k4A1 * 4 + 2][rA1] = v1.z; As[nb][k4A1 * 4 + 3][rA1] = v1.w;
            *(float4*)&Bs[nb][kkB0][c4B0 * 4] =
                *(const float4*)(B + (size_t)(kt + 16 + kkB0) * 128 + c4B0 * 4);
            *(float4*)&Bs[nb][kkB1][c4B1 * 4] =
                *(const float4*)(B + (size_t)(kt + 16 + kkB1) * 128 + c4B1 * 4);
        }
        // ---- compute on current buffer ----
#pragma unroll
        for (int k = 0; k < 16; k++) {
            float a[8], b[8];
            *(float4*)&a[0] = *(float4*)&As[buf][k][m0];
            *(float4*)&a[4] = *(float4*)&As[buf][k][m0 + 4];
            *(float4*)&b[0] = *(float4*)&Bs[buf][k][n0];
            *(float4*)&b[4] = *(float4*)&Bs[buf][k][n0 + 4];
#pragma unroll
            for (int i = 0; i < 8; i++)
#pragma unroll
                for (int j = 0; j < 8; j++) acc[i][j] += a[i] * b[j];
        }
        __syncthreads();
        buf ^= 1;
    }
#pragma unroll
    for (int i = 0; i < 8; i++) {
        int grow = rowBase + m0 + i;
        if (grow < M) {
            float o[8];
#pragma unroll
            for (int j = 0; j < 8; j++) {
                float v = acc[i][j];
                if (bias) v += bias[n0 + j];
                if (relu) v = fmaxf(v, 0.0f);
                o[j] = v;
            }
            *(float4*)(C + (size_t)grow * ldc + n0)     = *(float4*)&o[0];
            *(float4*)(C + (size_t)grow * ldc + n0 + 4) = *(float4*)&o[4];
        }
    }
}

// ---------------- fused edge MLP (CSR order) -------------------------------
// For a tile of 64 CSR positions: h1 = leaky(adst[dst]+asrc[src]+b1);
// out_tile = h1 @ W2; segmented per-column reduction -> atomicAdd into Y[:,0:128].
__global__ void edge_mlp_kernel(const float* __restrict__ adst,
                                const float* __restrict__ asrc,
                                const float* __restrict__ W2,
                                const float* __restrict__ b1,
                                float* __restrict__ Y) {
    __shared__ float Hs[64][128];
    __shared__ float Bs[16][128];
    __shared__ int sdst[64], ssrc[64];
    int tid = threadIdx.x;
    int p0 = blockIdx.x * 64;

    if (tid < 64) {
        sdst[tid] = g_csr_dst[p0 + tid];
        ssrc[tid] = g_csr_src[p0 + tid];
    }
    __syncthreads();

    // build h1 tile: 64 rows x 32 float4
#pragma unroll
    for (int it = 0; it < 16; it++) {
        int slot = tid + it * 128;             // 0..2047
        int r = slot >> 5, c4 = slot & 31;
        int d = sdst[r], s = ssrc[r];
        float4 va = *(const float4*)(adst + (size_t)d * HD + c4 * 4);
        float4 vb = *(const float4*)(asrc + (size_t)s * HD + c4 * 4);
        float4 bb = *(const float4*)(b1 + c4 * 4);
        float4 h;
        h.x = va.x + vb.x + bb.x;  h.x = (h.x > 0.f) ? h.x : 0.2f * h.x;
        h.y = va.y + vb.y + bb.y;  h.y = (h.y > 0.f) ? h.y : 0.2f * h.y;
        h.z = va.z + vb.z + bb.z;  h.z = (h.z > 0.f) ? h.z : 0.2f * h.z;
        h.w = va.w + vb.w + bb.w;  h.w = (h.w > 0.f) ? h.w : 0.2f * h.w;
        *(float4*)&Hs[r][c4 * 4] = h;
    }

    int tx = tid & 15, ty = tid >> 4;
    int m0 = ty * 8, n0 = tx * 8;
    float acc[8][8];
#pragma unroll
    for (int i = 0; i < 8; i++)
#pragma unroll
        for (int j = 0; j < 8; j++) acc[i][j] = 0.0f;

    for (int kt = 0; kt < 128; kt += 16) {
#pragma unroll
        for (int i = 0; i < 4; i++) {
            int slot = tid + i * 128;
            int kk = slot >> 5, c4 = slot & 31;
            *(float4*)&Bs[kk][c4 * 4] = *(const float4*)(W2 + (size_t)(kt + kk) * 128 + c4 * 4);
        }
        __syncthreads();
#pragma unroll
        for (int k = 0; k < 16; k++) {
            float a[8], b[8];
#pragma unroll
            for (int i = 0; i < 8; i++) a[i] = Hs[m0 + i][kt + k];
            *(float4*)&b[0] = *(float4*)&Bs[k][n0];
            *(float4*)&b[4] = *(float4*)&Bs[k][n0 + 4];
#pragma unroll
            for (int i = 0; i < 8; i++)
#pragma unroll
                for (int j = 0; j < 8; j++) acc[i][j] += a[i] * b[j];
        }
        __syncthreads();
    }

    // write out tile back into Hs (safe: Hs no longer needed)
#pragma unroll
    for (int i = 0; i < 8; i++) {
        *(float4*)&Hs[m0 + i][n0]     = *(float4*)&acc[i][0];
        *(float4*)&Hs[m0 + i][n0 + 4] = *(float4*)&acc[i][4];
    }
    __syncthreads();

    // per-column segmented reduction over dst runs (CSR-sorted tiles)
    int col = tid;  // 0..127
    int cur = sdst[0];
    float sum = 0.0f;
#pragma unroll 4
    for (int r = 0; r < 64; r++) {
        int d = sdst[r];
        if (d != cur) {
            atomicAdd(&Y[(size_t)cur * YS + col], sum);
            cur = d; sum = 0.0f;
        }
        sum += Hs[r][col];
    }
    atomicAdd(&Y[(size_t)cur * YS + col], sum);
}

// ---------------- normalized propagation: one warp per dst node ------------
__global__ void prop_kernel(const float* __restrict__ Yin, float* __restrict__ Yout) {
    int w = (blockIdx.x * blockDim.x + threadIdx.x) >> 5;
    int lane = threadIdx.x & 31;
    if (w >= NN) return;
    int p0 = g_rowptr[w], p1 = g_rowptr[w + 1];
    float4 acc = make_float4(0.f, 0.f, 0.f, 0.f);
#pragma unroll 4
    for (int p = p0; p < p1; p++) {
        int s = __ldg(&g_csr_src[p]);
        float wn = __ldg(&g_csr_norm[p]);
        float4 v = *(const float4*)(Yin + (size_t)s * YS + lane * 4);
        acc.x += wn * v.x; acc.y += wn * v.y; acc.z += wn * v.z; acc.w += wn * v.w;
    }
    *(float4*)(Yout + (size_t)w * YS + lane * 4) = acc;
}

// ---------------- host side ------------------------------------------------
extern "C" void kernel_launch(void* const* d_in, const int* in_sizes, int n_in,
                              void* d_out, int out_size) {
    const float* x     = (const float*)d_in[0];
    const void*  ei    = d_in[1];
    const float* W1    = (const float*)d_in[2];
    const float* b1    = (const float*)d_in[3];
    const float* W2    = (const float*)d_in[4];
    const float* b2    = (const float*)d_in[5];
    const float* tag_w = (const float*)d_in[6];
    const float* tag_b = (const float*)d_in[7];
    float*       out   = (float*)d_out;

    float *p_adst, *p_asrc, *p_Y;
    cudaGetSymbolAddress((void**)&p_adst, g_adst);
    cudaGetSymbolAddress((void**)&p_asrc, g_asrc);
    cudaGetSymbolAddress((void**)&p_Y,    g_Y);

    const int TB = 256;
    // ---- graph prep: dtype detect, degrees, norm, CSR ----
    detect_kernel<<<1, 32>>>((const int*)ei);
    zero_kernel<<<(NN + TB - 1) / TB, TB>>>();
    deg_kernel<<<(NE + TB - 1) / TB, TB>>>(ei);
    dinv_kernel<<<(NN + TB - 1) / TB, TB>>>();
    scan1_kernel<<<SCAN_NB, 1024>>>();
    scan2_kernel<<<1, 32>>>();
    scan3_kernel<<<(NN + TB - 1) / TB, TB>>>();
    fill_kernel<<<(NE + TB - 1) / TB, TB>>>(ei);

    // ---- MP layer: writes x0 directly into Y[:,0:128] ----
    int gemmGrid = (NN + 127) / 128;
    gemm128x128<<<gemmGrid, 256>>>(x, HD, W1,             nullptr, p_adst, HD, NN, HD, 0);
    gemm128x128<<<gemmGrid, 256>>>(x, HD, W1 + 128 * 128, nullptr, p_asrc, HD, NN, HD, 0);
    init_y0_kernel<<<(NN * 32 + TB - 1) / TB, TB>>>(b2);
    edge_mlp_kernel<<<NE / 64, 128>>>(p_adst, p_asrc, W2, b1, p_Y);

    // ---- TAG conv stack ----
    int propGrid = (NN * 32 + TB - 1) / TB;
    for (int l = 0; l < 3; l++) {
        for (int k = 1; k <= 3; k++) {
            prop_kernel<<<propGrid, TB>>>(p_Y + (k - 1) * HD, p_Y + k * HD);
        }
        const float* Bl = tag_w + (size_t)l * 4 * 128 * 128;  // contiguous [512,128]
        const float* bl = tag_b + (size_t)l * 128;
        if (l < 2) {
            // write new x into Y[:,0:128] in-place (each block writes only rows it read)
            gemm128x128<<<gemmGrid, 256>>>(p_Y, YS, Bl, bl, p_Y, YS, NN, 512, 1);
        } else {
            gemm128x128<<<gemmGrid, 256>>>(p_Y, YS, Bl, bl, out, HD, NN, 512, 1);
        }
    }
}

// round 12
// speedup vs baseline: 1.1628x; 1.1628x over previous
#include <cuda_runtime.h>

#define NN 50000
#define NE 800000
#define HD 128

// ---------------- scratch (device globals; no allocation allowed) ----------
__device__ int   g_is64;
__device__ int   g_deg[NN];
__device__ int   g_fill[NN];
__device__ float g_dinv[NN];
__device__ int   g_rowptr[NN + 1];
__device__ int   g_csr_src[NE];
__device__ int   g_csr_dst[NE];
__device__ float g_csr_norm[NE];
__device__ float g_adst[(size_t)NN * HD];   // x @ W1[0:128,:]
__device__ float g_asrc[(size_t)NN * HD];   // x @ W1[128:256,:]
__device__ float g_Y[(size_t)NN * 4 * HD];  // [x | A x | A^2 x | A^3 x], row stride 512
__device__ int   g_bsum[64];

#define SCAN_NB ((NN + 1023) / 1024)
#define YS 512   // row stride of g_Y in floats

// ---------------- packed f32x2 helpers (Blackwell dual fp32) ---------------
__device__ __forceinline__ unsigned long long pack_rep(float v) {
    unsigned long long r;
    asm("mov.b64 %0, {%1, %1};" : "=l"(r) : "f"(v));
    return r;
}
__device__ __forceinline__ unsigned long long pack2f(float lo, float hi) {
    unsigned long long r;
    asm("mov.b64 %0, {%1, %2};" : "=l"(r) : "f"(lo), "f"(hi));
    return r;
}
__device__ __forceinline__ void unpack2f(unsigned long long v, float& lo, float& hi) {
    asm("mov.b64 {%0, %1}, %2;" : "=f"(lo), "=f"(hi) : "l"(v));
}
__device__ __forceinline__ void fma2(unsigned long long& d, unsigned long long a,
                                     unsigned long long b) {
    asm("fma.rn.f32x2 %0, %1, %2, %0;" : "+l"(d) : "l"(a), "l"(b));
}

// ---------------- edge-index dtype detection -------------------------------
// jnp.int64 under default JAX config materializes as int32. Values < 50000,
// so if the buffer is truly int64(LE), every odd 32-bit word is 0. For int32,
// odd words are uniform random node ids — all-zero is impossible in practice.
__global__ void detect_kernel(const int* __restrict__ w) {
    if (threadIdx.x == 0) {
        int all0 = 1;
        for (int i = 1; i < 256; i += 2)
            if (w[i] != 0) all0 = 0;
        g_is64 = all0;
    }
}

__device__ __forceinline__ int load_idx(const void* ei, long long i, int is64) {
    if (is64) return (int)((const long long*)ei)[i];
    return ((const int*)ei)[i];
}

// ---------------- small prep kernels ---------------------------------------
__global__ void zero_kernel() {
    int i = blockIdx.x * blockDim.x + threadIdx.x;
    if (i < NN) { g_deg[i] = 0; g_fill[i] = 0; }
}

__global__ void deg_kernel(const void* __restrict__ ei) {
    int e = blockIdx.x * blockDim.x + threadIdx.x;
    int is64 = g_is64;
    if (e < NE) {
        int d = load_idx(ei, (long long)NE + e, is64);
        atomicAdd(&g_deg[d], 1);
    }
}

__global__ void dinv_kernel() {
    int n = blockIdx.x * blockDim.x + threadIdx.x;
    if (n < NN) {
        int dg = g_deg[n];
        g_dinv[n] = (dg > 0) ? rsqrtf((float)dg) : 0.0f;
    }
}

__global__ void scan1_kernel() {
    __shared__ int sh[1024];
    int i = blockIdx.x * 1024 + threadIdx.x;
    int v = (i < NN) ? g_deg[i] : 0;
    sh[threadIdx.x] = v;
    __syncthreads();
    for (int off = 1; off < 1024; off <<= 1) {
        int t = (threadIdx.x >= off) ? sh[threadIdx.x - off] : 0;
        __syncthreads();
        sh[threadIdx.x] += t;
        __syncthreads();
    }
    if (i < NN) g_rowptr[i] = sh[threadIdx.x] - v;  // exclusive within block
    if (threadIdx.x == 1023) g_bsum[blockIdx.x] = sh[1023];
}

__global__ void scan2_kernel() {
    if (threadIdx.x == 0) {
        int acc = 0;
        for (int b = 0; b < SCAN_NB; b++) { int t = g_bsum[b]; g_bsum[b] = acc; acc += t; }
    }
}

__global__ void scan3_kernel() {
    int i = blockIdx.x * blockDim.x + threadIdx.x;
    if (i < NN) g_rowptr[i] += g_bsum[i / 1024];
    if (i == 0) g_rowptr[NN] = NE;
}

__global__ void fill_kernel(const void* __restrict__ ei) {
    int e = blockIdx.x * blockDim.x + threadIdx.x;
    int is64 = g_is64;
    if (e < NE) {
        int s = load_idx(ei, e, is64);
        int d = load_idx(ei, (long long)NE + e, is64);
        int pos = g_rowptr[d] + atomicAdd(&g_fill[d], 1);
        g_csr_src[pos]  = s;
        g_csr_dst[pos]  = d;
        g_csr_norm[pos] = g_dinv[s] * g_dinv[d];
    }
}

// init Y[:,0:128] = deg[n] * b2  (per-edge bias b2 summed deg[n] times)
__global__ void init_y0_kernel(const float* __restrict__ b2) {
    int idx = blockIdx.x * blockDim.x + threadIdx.x;  // float4 units, NN*32 total
    if (idx < NN * 32) {
        int n = idx >> 5, c4 = idx & 31;
        float dg = (float)g_deg[n];
        float4 b = *(const float4*)(b2 + c4 * 4);
        float4 o; o.x = dg * b.x; o.y = dg * b.y; o.z = dg * b.z; o.w = dg * b.w;
        *(float4*)(g_Y + (size_t)n * YS + c4 * 4) = o;
    }
}

// ---------------- dense GEMM: C[M,128] = A[M,K] @ B[K,128] (+bias)(+relu) --
// BM=128, BN=128, BK=16, 256 threads, 8x8 per-thread tile, packed f32x2 FMA.
// A tile stored k-major (transposed) in smem; double-buffered smem tiles.
__global__ void gemm128x128(const float* __restrict__ A, int lda,
                            const float* __restrict__ B,
                            const float* __restrict__ bias,
                            float* __restrict__ C, int ldc,
                            int M, int K, int relu) {
    __shared__ float As[2][16][132];    // [buf][k][m], padded
    __shared__ float Bs[2][16][128];    // [buf][k][n]
    int tid = threadIdx.x;
    int tx = tid & 15, ty = tid >> 4;
    int m0 = ty * 8, n0 = tx * 8;
    int rowBase = blockIdx.x * 128;

    int slotA0 = tid * 2, slotA1 = tid * 2 + 1;
    int rA0 = slotA0 >> 2, k4A0 = slotA0 & 3;
    int rA1 = slotA1 >> 2, k4A1 = slotA1 & 3;
    int kkB0 = tid >> 5,         c4B0 = tid & 31;
    int kkB1 = (tid + 256) >> 5, c4B1 = (tid + 256) & 31;

    unsigned long long acc2[8][4];      // [i][j2], lanes (2*j2, 2*j2+1)
#pragma unroll
    for (int i = 0; i < 8; i++)
#pragma unroll
        for (int j = 0; j < 4; j++) acc2[i][j] = 0ull;

    // ---- load tile 0 into buffer 0 ----
    {
        int grow0 = rowBase + rA0, grow1 = rowBase + rA1;
        float4 v0 = make_float4(0.f, 0.f, 0.f, 0.f);
        float4 v1 = make_float4(0.f, 0.f, 0.f, 0.f);
        if (grow0 < M) v0 = *(const float4*)(A + (size_t)grow0 * lda + k4A0 * 4);
        if (grow1 < M) v1 = *(const float4*)(A + (size_t)grow1 * lda + k4A1 * 4);
        As[0][k4A0 * 4 + 0][rA0] = v0.x; As[0][k4A0 * 4 + 1][rA0] = v0.y;
        As[0][k4A0 * 4 + 2][rA0] = v0.z; As[0][k4A0 * 4 + 3][rA0] = v0.w;
        As[0][k4A1 * 4 + 0][rA1] = v1.x; As[0][k4A1 * 4 + 1][rA1] = v1.y;
        As[0][k4A1 * 4 + 2][rA1] = v1.z; As[0][k4A1 * 4 + 3][rA1] = v1.w;
        *(float4*)&Bs[0][kkB0][c4B0 * 4] = *(const float4*)(B + (size_t)kkB0 * 128 + c4B0 * 4);
        *(float4*)&Bs[0][kkB1][c4B1 * 4] = *(const float4*)(B + (size_t)kkB1 * 128 + c4B1 * 4);
    }
    __syncthreads();

    int buf = 0;
    for (int kt = 0; kt < K; kt += 16) {
        // ---- prefetch next tile into buf^1 (overlaps with compute) ----
        if (kt + 16 < K) {
            int nb = buf ^ 1;
            int grow0 = rowBase + rA0, grow1 = rowBase + rA1;
            float4 v0 = make_float4(0.f, 0.f, 0.f, 0.f);
            float4 v1 = make_float4(0.f, 0.f, 0.f, 0.f);
            if (grow0 < M) v0 = *(const float4*)(A + (size_t)grow0 * lda + kt + 16 + k4A0 * 4);
            if (grow1 < M) v1 = *(const float4*)(A + (size_t)grow1 * lda + kt + 16 + k4A1 * 4);
            As[nb][k4A0 * 4 + 0][rA0] = v0.x; As[nb][k4A0 * 4 + 1][rA0] = v0.y;
            As[nb][k4A0 * 4 + 2][rA0] = v0.z; As[nb][k4A0 * 4 + 3][rA0] = v0.w;
            As[nb][k4A1 * 4 + 0][rA1] = v1.x; As[nb][k4A1 * 4 + 1][rA1] = v1.y;
            As[nb][k4A1 * 4 + 2][rA1] = v1.z; As[nb][k4A1 * 4 + 3][rA1] = v1.w;
            *(float4*)&Bs[nb][kkB0][c4B0 * 4] =
                *(const float4*)(B + (size_t)(kt + 16 + kkB0) * 128 + c4B0 * 4);
            *(float4*)&Bs[nb][kkB1][c4B1 * 4] =
                *(const float4*)(B + (size_t)(kt + 16 + kkB1) * 128 + c4B1 * 4);
        }
        // ---- compute on current buffer (packed f32x2) ----
#pragma unroll
        for (int k = 0; k < 16; k++) {
            float a[8], b[8];
            *(float4*)&a[0] = *(float4*)&As[buf][k][m0];
            *(float4*)&a[4] = *(float4*)&As[buf][k][m0 + 4];
            *(float4*)&b[0] = *(float4*)&Bs[buf][k][n0];
            *(float4*)&b[4] = *(float4*)&Bs[buf][k][n0 + 4];
            unsigned long long bp[4];
#pragma unroll
            for (int j = 0; j < 4; j++) bp[j] = pack2f(b[2 * j], b[2 * j + 1]);
#pragma unroll
            for (int i = 0; i < 8; i++) {
                unsigned long long ap = pack_rep(a[i]);
#pragma unroll
                for (int j = 0; j < 4; j++) fma2(acc2[i][j], ap, bp[j]);
            }
        }
        __syncthreads();
        buf ^= 1;
    }
#pragma unroll
    for (int i = 0; i < 8; i++) {
        int grow = rowBase + m0 + i;
        if (grow < M) {
            float o[8];
#pragma unroll
            for (int j = 0; j < 4; j++) unpack2f(acc2[i][j], o[2 * j], o[2 * j + 1]);
#pragma unroll
            for (int j = 0; j < 8; j++) {
                float v = o[j];
                if (bias) v += bias[n0 + j];
                if (relu) v = fmaxf(v, 0.0f);
                o[j] = v;
            }
            *(float4*)(C + (size_t)grow * ldc + n0)     = *(float4*)&o[0];
            *(float4*)(C + (size_t)grow * ldc + n0 + 4) = *(float4*)&o[4];
        }
    }
}

// ---------------- fused edge MLP (CSR order) -------------------------------
// For a tile of 64 CSR positions: h1 = leaky(adst[dst]+asrc[src]+b1);
// out_tile = h1 @ W2; segmented per-column reduction -> atomicAdd into Y[:,0:128].
__global__ void edge_mlp_kernel(const float* __restrict__ adst,
                                const float* __restrict__ asrc,
                                const float* __restrict__ W2,
                                const float* __restrict__ b1,
                                float* __restrict__ Y) {
    __shared__ float Hs[64][128];
    __shared__ float Bs[16][128];
    __shared__ int sdst[64], ssrc[64];
    int tid = threadIdx.x;
    int p0 = blockIdx.x * 64;

    if (tid < 64) {
        sdst[tid] = g_csr_dst[p0 + tid];
        ssrc[tid] = g_csr_src[p0 + tid];
    }
    __syncthreads();

    // build h1 tile: 64 rows x 32 float4
#pragma unroll
    for (int it = 0; it < 16; it++) {
        int slot = tid + it * 128;             // 0..2047
        int r = slot >> 5, c4 = slot & 31;
        int d = sdst[r], s = ssrc[r];
        float4 va = *(const float4*)(adst + (size_t)d * HD + c4 * 4);
        float4 vb = *(const float4*)(asrc + (size_t)s * HD + c4 * 4);
        float4 bb = *(const float4*)(b1 + c4 * 4);
        float4 h;
        h.x = va.x + vb.x + bb.x;  h.x = (h.x > 0.f) ? h.x : 0.2f * h.x;
        h.y = va.y + vb.y + bb.y;  h.y = (h.y > 0.f) ? h.y : 0.2f * h.y;
        h.z = va.z + vb.z + bb.z;  h.z = (h.z > 0.f) ? h.z : 0.2f * h.z;
        h.w = va.w + vb.w + bb.w;  h.w = (h.w > 0.f) ? h.w : 0.2f * h.w;
        *(float4*)&Hs[r][c4 * 4] = h;
    }

    int tx = tid & 15, ty = tid >> 4;
    int m0 = ty * 8, n0 = tx * 8;
    unsigned long long acc2[8][4];
#pragma unroll
    for (int i = 0; i < 8; i++)
#pragma unroll
        for (int j = 0; j < 4; j++) acc2[i][j] = 0ull;

    for (int kt = 0; kt < 128; kt += 16) {
#pragma unroll
        for (int i = 0; i < 4; i++) {
            int slot = tid + i * 128;
            int kk = slot >> 5, c4 = slot & 31;
            *(float4*)&Bs[kk][c4 * 4] = *(const float4*)(W2 + (size_t)(kt + kk) * 128 + c4 * 4);
        }
        __syncthreads();
#pragma unroll
        for (int k = 0; k < 16; k++) {
            float a[8], b[8];
#pragma unroll
            for (int i = 0; i < 8; i++) a[i] = Hs[m0 + i][kt + k];
            *(float4*)&b[0] = *(float4*)&Bs[k][n0];
            *(float4*)&b[4] = *(float4*)&Bs[k][n0 + 4];
            unsigned long long bp[4];
#pragma unroll
            for (int j = 0; j < 4; j++) bp[j] = pack2f(b[2 * j], b[2 * j + 1]);
#pragma unroll
            for (int i = 0; i < 8; i++) {
                unsigned long long ap = pack_rep(a[i]);
#pragma unroll
                for (int j = 0; j < 4; j++) fma2(acc2[i][j], ap, bp[j]);
            }
        }
        __syncthreads();
    }

    // write out tile back into Hs (safe: Hs no longer needed)
#pragma unroll
    for (int i = 0; i < 8; i++) {
        float o[8];
#pragma unroll
        for (int j = 0; j < 4; j++) unpack2f(acc2[i][j], o[2 * j], o[2 * j + 1]);
        *(float4*)&Hs[m0 + i][n0]     = *(float4*)&o[0];
        *(float4*)&Hs[m0 + i][n0 + 4] = *(float4*)&o[4];
    }
    __syncthreads();

    // per-column segmented reduction over dst runs (CSR-sorted tiles)
    int col = tid;  // 0..127
    int cur = sdst[0];
    float sum = 0.0f;
#pragma unroll 4
    for (int r = 0; r < 64; r++) {
        int d = sdst[r];
        if (d != cur) {
            atomicAdd(&Y[(size_t)cur * YS + col], sum);
            cur = d; sum = 0.0f;
        }
        sum += Hs[r][col];
    }
    atomicAdd(&Y[(size_t)cur * YS + col], sum);
}

// ---------------- normalized propagation: one warp per dst node ------------
__global__ void prop_kernel(const float* __restrict__ Yin, float* __restrict__ Yout) {
    int w = (blockIdx.x * blockDim.x + threadIdx.x) >> 5;
    int lane = threadIdx.x & 31;
    if (w >= NN) return;
    int p0 = g_rowptr[w], p1 = g_rowptr[w + 1];
    float4 acc = make_float4(0.f, 0.f, 0.f, 0.f);
#pragma unroll 4
    for (int p = p0; p < p1; p++) {
        int s = __ldg(&g_csr_src[p]);
        float wn = __ldg(&g_csr_norm[p]);
        float4 v = *(const float4*)(Yin + (size_t)s * YS + lane * 4);
        acc.x += wn * v.x; acc.y += wn * v.y; acc.z += wn * v.z; acc.w += wn * v.w;
    }
    *(float4*)(Yout + (size_t)w * YS + lane * 4) = acc;
}

// ---------------- host side ------------------------------------------------
extern "C" void kernel_launch(void* const* d_in, const int* in_sizes, int n_in,
                              void* d_out, int out_size) {
    const float* x     = (const float*)d_in[0];
    const void*  ei    = d_in[1];
    const float* W1    = (const float*)d_in[2];
    const float* b1    = (const float*)d_in[3];
    const float* W2    = (const float*)d_in[4];
    const float* b2    = (const float*)d_in[5];
    const float* tag_w = (const float*)d_in[6];
    const float* tag_b = (const float*)d_in[7];
    float*       out   = (float*)d_out;

    float *p_adst, *p_asrc, *p_Y;
    cudaGetSymbolAddress((void**)&p_adst, g_adst);
    cudaGetSymbolAddress((void**)&p_asrc, g_asrc);
    cudaGetSymbolAddress((void**)&p_Y,    g_Y);

    const int TB = 256;
    int gemmGrid = (NN + 127) / 128;

    // ---- launches 0-3: detect, zero, then the two MP GEMMs (so ncu's
    //      skip-capture lands on a GEMM instead of a tiny prep kernel) ----
    detect_kernel<<<1, 32>>>((const int*)ei);
    zero_kernel<<<(NN + TB - 1) / TB, TB>>>();
    gemm128x128<<<gemmGrid, 256>>>(x, HD, W1,             nullptr, p_adst, HD, NN, HD, 0);
    gemm128x128<<<gemmGrid, 256>>>(x, HD, W1 + 128 * 128, nullptr, p_asrc, HD, NN, HD, 0);

    // ---- graph prep: degrees, norm, CSR ----
    deg_kernel<<<(NE + TB - 1) / TB, TB>>>(ei);
    dinv_kernel<<<(NN + TB - 1) / TB, TB>>>();
    scan1_kernel<<<SCAN_NB, 1024>>>();
    scan2_kernel<<<1, 32>>>();
    scan3_kernel<<<(NN + TB - 1) / TB, TB>>>();
    fill_kernel<<<(NE + TB - 1) / TB, TB>>>(ei);

    // ---- MP layer: writes x0 directly into Y[:,0:128] ----
    init_y0_kernel<<<(NN * 32 + TB - 1) / TB, TB>>>(b2);
    edge_mlp_kernel<<<NE / 64, 128>>>(p_adst, p_asrc, W2, b1, p_Y);

    // ---- TAG conv stack ----
    int propGrid = (NN * 32 + TB - 1) / TB;
    for (int l = 0; l < 3; l++) {
        for (int k = 1; k <= 3; k++) {
            prop_kernel<<<propGrid, TB>>>(p_Y + (k - 1) * HD, p_Y + k * HD);
        }
        const float* Bl = tag_w + (size_t)l * 4 * 128 * 128;  // contiguous [512,128]
        const float* bl = tag_b + (size_t)l * 128;
        if (l < 2) {
            // write new x into Y[:,0:128] in-place (each block writes only rows it read)
            gemm128x128<<<gemmGrid, 256>>>(p_Y, YS, Bl, bl, p_Y, YS, NN, 512, 1);
        } else {
            gemm128x128<<<gemmGrid, 256>>>(p_Y, YS, Bl, bl, out, HD, NN, 512, 1);
        }
    }
}